// round 13
// baseline (speedup 1.0000x reference)
#include <cuda_runtime.h>
#include <cuda_bf16.h>
#include <cstdint>

// ---------------- problem constants ----------------
#define TOK    32768
#define BHW    8192
#define NSEG   4
#define INDIM  1536
#define HID    768
#define NHEAD  8
#define HD     96

// ---------------- scratch ----------------
__device__ float g_q[(size_t)TOK * HID];
__device__ float g_k[(size_t)TOK * HID];
__device__ float g_v[(size_t)TOK * HID];
__device__ __nv_bfloat16 g_x_hi[(size_t)TOK * INDIM];
__device__ __nv_bfloat16 g_x_lo[(size_t)TOK * INDIM];
__device__ __nv_bfloat16 g_oh[(size_t)TOK * HID];
__device__ __nv_bfloat16 g_ol[(size_t)TOK * HID];
__device__ __nv_bfloat16 g_wq_hi[(size_t)HID * INDIM];
__device__ __nv_bfloat16 g_wq_lo[(size_t)HID * INDIM];
__device__ __nv_bfloat16 g_wk_hi[(size_t)HID * INDIM];
__device__ __nv_bfloat16 g_wk_lo[(size_t)HID * INDIM];
__device__ __nv_bfloat16 g_wv_hi[(size_t)HID * INDIM];
__device__ __nv_bfloat16 g_wv_lo[(size_t)HID * INDIM];
__device__ __nv_bfloat16 g_wo_hi[(size_t)INDIM * HID];
__device__ __nv_bfloat16 g_wo_lo[(size_t)INDIM * HID];

// ---------------- helpers ----------------
__device__ __forceinline__ uint32_t smem_u32(const void* p) {
    uint32_t a;
    asm("{ .reg .u64 t; cvta.to.shared.u64 t, %1; cvt.u32.u64 %0, t; }" : "=r"(a) : "l"(p));
    return a;
}

__device__ __forceinline__ void cp16(uint32_t dst, const void* src) {
    asm volatile("cp.async.cg.shared.global [%0], [%1], 16;" :: "r"(dst), "l"(src) : "memory");
}
#define CP_COMMIT() asm volatile("cp.async.commit_group;" ::: "memory")
#define CP_WAIT(n)  asm volatile("cp.async.wait_group %0;" :: "n"(n) : "memory")

#define LDSM_X4(r, a) \
    asm volatile("ldmatrix.sync.aligned.m8n8.x4.shared.b16 {%0,%1,%2,%3}, [%4];" \
        : "=r"((r)[0]), "=r"((r)[1]), "=r"((r)[2]), "=r"((r)[3]) : "r"(a))

__device__ __forceinline__ void mma16816(float* d, const uint32_t* a, uint32_t b0, uint32_t b1) {
    asm volatile("mma.sync.aligned.m16n8k16.row.col.f32.bf16.bf16.f32 "
        "{%0,%1,%2,%3}, {%4,%5,%6,%7}, {%8,%9}, {%0,%1,%2,%3};"
        : "+f"(d[0]), "+f"(d[1]), "+f"(d[2]), "+f"(d[3])
        : "r"(a[0]), "r"(a[1]), "r"(a[2]), "r"(a[3]), "r"(b0), "r"(b1));
}

__device__ __forceinline__ uint32_t split2(float a, float b, uint32_t& lo) {
    __nv_bfloat16 ha = __float2bfloat16_rn(a), hb = __float2bfloat16_rn(b);
    float ra = a - __bfloat162float(ha), rb = b - __bfloat162float(hb);
    __nv_bfloat16 la = __float2bfloat16_rn(ra), lb = __float2bfloat16_rn(rb);
    lo = (uint32_t)(*(uint16_t*)&la) | ((uint32_t)(*(uint16_t*)&lb) << 16);
    return (uint32_t)(*(uint16_t*)&ha) | ((uint32_t)(*(uint16_t*)&hb) << 16);
}

// =====================================================================
// conversions (one-time per launch)
// =====================================================================
__global__ void convert_x(const float* __restrict__ x)
{
    size_t i2 = (size_t)blockIdx.x * 256 + threadIdx.x;
    size_t idx = i2 * 2;
    int d  = (int)(idx & 63);
    int hw = (int)((idx >> 6) & 1023);
    int r  = (int)(idx >> 16);        // b*96 + t
    int t  = r % 96, b = r / 96;
    int sg = t / 24, p = t - sg * 24;
    int m  = ((b * 1024 + hw) << 2) + sg;
    int k  = p * 64 + d;
    float2 v = *(const float2*)(x + idx);
    uint32_t lo, hi = split2(v.x, v.y, lo);
    size_t o = (size_t)m * INDIM + k;
    *(uint32_t*)(g_x_hi + o) = hi;
    *(uint32_t*)(g_x_lo + o) = lo;
}

__global__ void convert_qkv(const float* __restrict__ Wq,
                            const float* __restrict__ Wk,
                            const float* __restrict__ Wv)
{
    const int z = blockIdx.y;
    const float* W = (z == 0) ? Wq : ((z == 1) ? Wk : Wv);
    __nv_bfloat16* oh = (z == 0) ? g_wq_hi : ((z == 1) ? g_wk_hi : g_wv_hi);
    __nv_bfloat16* ol = (z == 0) ? g_wq_lo : ((z == 1) ? g_wk_lo : g_wv_lo);
    int idx = blockIdx.x * 256 + threadIdx.x;      // n*INDIM + k
    int n = idx / INDIM, k = idx - n * INDIM;
    float v = W[(size_t)k * HID + n];
    __nv_bfloat16 h = __float2bfloat16_rn(v);
    oh[idx] = h;
    ol[idx] = __float2bfloat16_rn(v - __bfloat162float(h));
}

__global__ void convert_wo(const float* __restrict__ Wo)
{
    int idx = blockIdx.x * 256 + threadIdx.x;      // e*HID + k
    int e = idx / HID, k = idx - e * HID;
    float v = Wo[(size_t)k * INDIM + e];
    __nv_bfloat16 h = __float2bfloat16_rn(v);
    g_wo_hi[idx] = h;
    g_wo_lo[idx] = __float2bfloat16_rn(v - __bfloat162float(h));
}

// =====================================================================
// Kernel 1: QKV GEMM, mma.sync bf16 split-3, pass-major MMA order.
// CTA tile 128(M)x64(N), K-chunk 16, 3 stages, 256 threads, 3 CTAs/SM.
// grid (12, 256, 3).
// =====================================================================
__global__ __launch_bounds__(256, 3) void gemm_qkv_mma()
{
    __shared__ __nv_bfloat16 sAh[3][128][24];
    __shared__ __nv_bfloat16 sAl[3][128][24];
    __shared__ __nv_bfloat16 sBh[3][64][24];
    __shared__ __nv_bfloat16 sBl[3][64][24];

    const int tid = threadIdx.x;
    const int n0 = blockIdx.x * 64, m0 = blockIdx.y * 128, z = blockIdx.z;
    const __nv_bfloat16* Bhi = (z == 0) ? g_wq_hi : ((z == 1) ? g_wk_hi : g_wv_hi);
    const __nv_bfloat16* Blo = (z == 0) ? g_wq_lo : ((z == 1) ? g_wk_lo : g_wv_lo);
    float* C = (z == 0) ? g_q : ((z == 1) ? g_k : g_v);

    const int arow = tid >> 1, ahalf = tid & 1;
    const int brow = tid >> 2, bhalf = (tid >> 1) & 1, bgrp = tid & 1;
    const __nv_bfloat16* asrch = g_x_hi + (size_t)(m0 + arow) * INDIM + ahalf * 8;
    const __nv_bfloat16* asrcl = g_x_lo + (size_t)(m0 + arow) * INDIM + ahalf * 8;
    const __nv_bfloat16* bsrc  = (bgrp ? Blo : Bhi) + (size_t)(n0 + brow) * INDIM + bhalf * 8;

    const int wid = tid >> 5, lane = tid & 31;
    const int wm = wid & 3, wn = wid >> 2;
    const int aldr = wm * 32 + (lane & 15);
    const int aldc = (lane >> 4) * 8;
    const int bldr = wn * 32 + ((lane >> 4) & 1) * 8 + (lane & 7);
    const int bldc = ((lane >> 3) & 1) * 8;

    float acc[2][4][4];
    #pragma unroll
    for (int mi = 0; mi < 2; mi++)
        #pragma unroll
        for (int ni = 0; ni < 4; ni++)
            #pragma unroll
            for (int q = 0; q < 4; q++) acc[mi][ni][q] = 0.f;

    const int NC = INDIM / 16;   // 96

    #define STAGE(st, c) do {                                                     \
        cp16(smem_u32(&sAh[st][arow][ahalf * 8]), asrch + (c) * 16);              \
        cp16(smem_u32(&sAl[st][arow][ahalf * 8]), asrcl + (c) * 16);              \
        cp16(smem_u32(&(bgrp ? sBl : sBh)[st][brow][bhalf * 8]), bsrc + (c) * 16);\
    } while (0)

    STAGE(0, 0); CP_COMMIT();
    STAGE(1, 1); CP_COMMIT();

    int sc_ = 0;   // stage of chunk c
    for (int c = 0; c < NC; c++) {
        CP_WAIT(1);
        __syncthreads();
        int sn = sc_ + 2; if (sn >= 3) sn -= 3;
        if (c + 2 < NC) { STAGE(sn, c + 2); CP_COMMIT(); }

        uint32_t ah[2][4], al[2][4], bh[2][4], bl[2][4];
        #pragma unroll
        for (int mi = 0; mi < 2; mi++) {
            LDSM_X4(ah[mi], smem_u32(&sAh[sc_][aldr + mi * 16][aldc]));
            LDSM_X4(al[mi], smem_u32(&sAl[sc_][aldr + mi * 16][aldc]));
        }
        #pragma unroll
        for (int g = 0; g < 2; g++) {
            LDSM_X4(bh[g], smem_u32(&sBh[sc_][bldr + g * 16][bldc]));
            LDSM_X4(bl[g], smem_u32(&sBl[sc_][bldr + g * 16][bldc]));
        }
        // pass-major: 8 independent MMAs between accumulator reuses
        #pragma unroll
        for (int mi = 0; mi < 2; mi++)
            #pragma unroll
            for (int ni = 0; ni < 4; ni++)
                mma16816(acc[mi][ni], ah[mi],
                         bh[ni >> 1][(ni & 1) * 2], bh[ni >> 1][(ni & 1) * 2 + 1]);
        #pragma unroll
        for (int mi = 0; mi < 2; mi++)
            #pragma unroll
            for (int ni = 0; ni < 4; ni++)
                mma16816(acc[mi][ni], ah[mi],
                         bl[ni >> 1][(ni & 1) * 2], bl[ni >> 1][(ni & 1) * 2 + 1]);
        #pragma unroll
        for (int mi = 0; mi < 2; mi++)
            #pragma unroll
            for (int ni = 0; ni < 4; ni++)
                mma16816(acc[mi][ni], al[mi],
                         bh[ni >> 1][(ni & 1) * 2], bh[ni >> 1][(ni & 1) * 2 + 1]);
        if (++sc_ == 3) sc_ = 0;
    }
    #undef STAGE

    // epilogue: contiguous fp32 stores
    #pragma unroll
    for (int mi = 0; mi < 2; mi++) {
        int r = m0 + wm * 32 + mi * 16 + (lane >> 2);
        #pragma unroll
        for (int ni = 0; ni < 4; ni++) {
            int cg = n0 + wn * 32 + ni * 8 + (lane & 3) * 2;
            *(float2*)(C + (size_t)r * HID + cg)       = make_float2(acc[mi][ni][0], acc[mi][ni][1]);
            *(float2*)(C + (size_t)(r + 8) * HID + cg) = make_float2(acc[mi][ni][2], acc[mi][ni][3]);
        }
    }
}

// =====================================================================
// Kernel 2: RoPE + tiny attention; emits o as bf16 hi/lo.
// =====================================================================
__global__ __launch_bounds__(256)
void attn_kernel(const float* __restrict__ fcos, const float* __restrict__ fsin)
{
    __shared__ float sq[NSEG][HID];
    __shared__ float sk[NSEG][HID];
    __shared__ float sv[NSEG][HID];

    const int bhw = blockIdx.x;
    const int tid = threadIdx.x;
    const long base = (long)bhw * NSEG * HID;

    for (int idx = tid; idx < NSEG * (HID / 2); idx += 256) {
        int i = idx / (HID / 2);
        int j = idx - i * (HID / 2);
        float c = fcos[i * (HID / 2) + j];
        float s = fsin[i * (HID / 2) + j];
        float2 q2 = *(const float2*)(g_q + base + (long)i * HID + 2 * j);
        float2 k2 = *(const float2*)(g_k + base + (long)i * HID + 2 * j);
        sq[i][2 * j]     = q2.x * c - q2.y * s;
        sq[i][2 * j + 1] = q2.x * s + q2.y * c;
        sk[i][2 * j]     = k2.x * c - k2.y * s;
        sk[i][2 * j + 1] = k2.x * s + k2.y * c;
        float2 v2 = *(const float2*)(g_v + base + (long)i * HID + 2 * j);
        *(float2*)&sv[i][2 * j] = v2;
    }
    __syncthreads();

    const int w = tid >> 5;
    const int lane = tid & 31;
    const int cb = w * HD;

    float sc[4][4];
    #pragma unroll
    for (int i = 0; i < 4; i++)
        #pragma unroll
        for (int j = 0; j < 4; j++) {
            float p = 0.f;
            #pragma unroll
            for (int t = 0; t < 3; t++) {
                int d = lane + 32 * t;
                p += sq[i][cb + d] * sk[j][cb + d];
            }
            sc[i][j] = p;
        }
    #pragma unroll
    for (int i = 0; i < 4; i++)
        #pragma unroll
        for (int j = 0; j < 4; j++)
            #pragma unroll
            for (int off = 16; off > 0; off >>= 1)
                sc[i][j] += __shfl_xor_sync(0xffffffffu, sc[i][j], off);

    const float scale = 0.10206207261596577f;   // 1/sqrt(96)
    float attn[4][4];
    #pragma unroll
    for (int i = 0; i < 4; i++) {
        float mx = -1e30f;
        #pragma unroll
        for (int j = 0; j < 4; j++) { sc[i][j] *= scale; mx = fmaxf(mx, sc[i][j]); }
        float sum = 0.f;
        #pragma unroll
        for (int j = 0; j < 4; j++) { attn[i][j] = expf(sc[i][j] - mx); sum += attn[i][j]; }
        float inv = 1.f / sum;
        #pragma unroll
        for (int j = 0; j < 4; j++) attn[i][j] *= inv;
    }

    #pragma unroll
    for (int i = 0; i < 4; i++) {
        #pragma unroll
        for (int t = 0; t < 3; t++) {
            int d = lane + 32 * t;
            float o = 0.f;
            #pragma unroll
            for (int j = 0; j < 4; j++) o += attn[i][j] * sv[j][cb + d];
            long oi = base + (long)i * HID + cb + d;
            __nv_bfloat16 h = __float2bfloat16_rn(o);
            g_oh[oi] = h;
            g_ol[oi] = __float2bfloat16_rn(o - __bfloat162float(h));
        }
    }
}

// =====================================================================
// Kernel 3: O-proj GEMM, mma.sync bf16 split-3, pass-major MMA order.
// CTA tile 128x64, K-chunk 16, 3 stages, 256 threads, 3 CTAs/SM.
// grid (24, 256).
// =====================================================================
__global__ __launch_bounds__(256, 3) void gemm_o_mma(const float* __restrict__ bo,
                                                     float* __restrict__ out)
{
    __shared__ __nv_bfloat16 sAh[3][128][24];
    __shared__ __nv_bfloat16 sAl[3][128][24];
    __shared__ __nv_bfloat16 sBh[3][64][24];
    __shared__ __nv_bfloat16 sBl[3][64][24];

    const int tid = threadIdx.x;
    const int n0 = blockIdx.x * 64, m0 = blockIdx.y * 128;

    const int arow = tid >> 1, ahalf = tid & 1;
    const int brow = tid >> 2, bhalf = (tid >> 1) & 1, bgrp = tid & 1;
    const __nv_bfloat16* asrch = g_oh + (size_t)(m0 + arow) * HID + ahalf * 8;
    const __nv_bfloat16* asrcl = g_ol + (size_t)(m0 + arow) * HID + ahalf * 8;
    const __nv_bfloat16* bsrc  = (bgrp ? g_wo_lo : g_wo_hi) + (size_t)(n0 + brow) * HID + bhalf * 8;

    const int wid = tid >> 5, lane = tid & 31;
    const int wm = wid & 3, wn = wid >> 2;
    const int aldr = wm * 32 + (lane & 15);
    const int aldc = (lane >> 4) * 8;
    const int bldr = wn * 32 + ((lane >> 4) & 1) * 8 + (lane & 7);
    const int bldc = ((lane >> 3) & 1) * 8;

    float acc[2][4][4];
    #pragma unroll
    for (int mi = 0; mi < 2; mi++)
        #pragma unroll
        for (int ni = 0; ni < 4; ni++)
            #pragma unroll
            for (int q = 0; q < 4; q++) acc[mi][ni][q] = 0.f;

    const int NC = HID / 16;   // 48

    #define STAGE(st, c) do {                                                     \
        cp16(smem_u32(&sAh[st][arow][ahalf * 8]), asrch + (c) * 16);              \
        cp16(smem_u32(&sAl[st][arow][ahalf * 8]), asrcl + (c) * 16);              \
        cp16(smem_u32(&(bgrp ? sBl : sBh)[st][brow][bhalf * 8]), bsrc + (c) * 16);\
    } while (0)

    STAGE(0, 0); CP_COMMIT();
    STAGE(1, 1); CP_COMMIT();

    int sc_ = 0;
    for (int c = 0; c < NC; c++) {
        CP_WAIT(1);
        __syncthreads();
        int sn = sc_ + 2; if (sn >= 3) sn -= 3;
        if (c + 2 < NC) { STAGE(sn, c + 2); CP_COMMIT(); }

        uint32_t ah[2][4], al[2][4], bh[2][4], bl[2][4];
        #pragma unroll
        for (int mi = 0; mi < 2; mi++) {
            LDSM_X4(ah[mi], smem_u32(&sAh[sc_][aldr + mi * 16][aldc]));
            LDSM_X4(al[mi], smem_u32(&sAl[sc_][aldr + mi * 16][aldc]));
        }
        #pragma unroll
        for (int g = 0; g < 2; g++) {
            LDSM_X4(bh[g], smem_u32(&sBh[sc_][bldr + g * 16][bldc]));
            LDSM_X4(bl[g], smem_u32(&sBl[sc_][bldr + g * 16][bldc]));
        }
        #pragma unroll
        for (int mi = 0; mi < 2; mi++)
            #pragma unroll
            for (int ni = 0; ni < 4; ni++)
                mma16816(acc[mi][ni], ah[mi],
                         bh[ni >> 1][(ni & 1) * 2], bh[ni >> 1][(ni & 1) * 2 + 1]);
        #pragma unroll
        for (int mi = 0; mi < 2; mi++)
            #pragma unroll
            for (int ni = 0; ni < 4; ni++)
                mma16816(acc[mi][ni], ah[mi],
                         bl[ni >> 1][(ni & 1) * 2], bl[ni >> 1][(ni & 1) * 2 + 1]);
        #pragma unroll
        for (int mi = 0; mi < 2; mi++)
            #pragma unroll
            for (int ni = 0; ni < 4; ni++)
                mma16816(acc[mi][ni], al[mi],
                         bh[ni >> 1][(ni & 1) * 2], bh[ni >> 1][(ni & 1) * 2 + 1]);
        if (++sc_ == 3) sc_ = 0;
    }
    #undef STAGE

    // epilogue: + bias, scatter to (B,T,H,W,D)
    #pragma unroll
    for (int mi = 0; mi < 2; mi++) {
        #pragma unroll
        for (int half = 0; half < 2; half++) {
            int m = m0 + wm * 32 + mi * 16 + (lane >> 2) + half * 8;
            int bhw = m >> 2, sg = m & 3, b = bhw >> 10, hw = bhw & 1023;
            long baseO = ((long)(b * 96 + sg * 24) * 1024 + hw) * 64;
            #pragma unroll
            for (int ni = 0; ni < 4; ni++) {
                int e = n0 + wn * 32 + ni * 8 + (lane & 3) * 2;
                int p = e >> 6, d = e & 63;
                float2 bb = *(const float2*)(bo + e);
                float2 v = make_float2(acc[mi][ni][half * 2]     + bb.x,
                                       acc[mi][ni][half * 2 + 1] + bb.y);
                *(float2*)(out + baseO + (long)p * 65536 + d) = v;
            }
        }
    }
}

// =====================================================================
extern "C" void kernel_launch(void* const* d_in, const int* in_sizes, int n_in,
                              void* d_out, int out_size)
{
    const float* x  = (const float*)d_in[0];
    const float* fc = (const float*)d_in[1];
    const float* fs = (const float*)d_in[2];
    const float* Wq = (const float*)d_in[3];
    const float* Wk = (const float*)d_in[4];
    const float* Wv = (const float*)d_in[5];
    const float* Wo = (const float*)d_in[6];
    const float* bo = (const float*)d_in[7];
    float* out = (float*)d_out;

    convert_qkv<<<dim3((HID * INDIM) / 256, 3), 256>>>(Wq, Wk, Wv);
    convert_wo<<<(INDIM * HID) / 256, 256>>>(Wo);
    convert_x<<<(TOK * (size_t)INDIM / 2) / 256, 256>>>(x);
    gemm_qkv_mma<<<dim3(HID / 64, TOK / 128, 3), 256>>>();
    attn_kernel<<<BHW, 256>>>(fc, fs);
    gemm_o_mma<<<dim3(INDIM / 64, TOK / 128), 256>>>(bo, out);
}

// round 14
// speedup vs baseline: 1.0002x; 1.0002x over previous
#include <cuda_runtime.h>
#include <cuda_bf16.h>
#include <cstdint>

// ---------------- problem constants ----------------
#define TOK    32768
#define BHW    8192
#define NSEG   4
#define INDIM  1536
#define HID    768
#define NHEAD  8
#define HD     96

// ---------------- scratch ----------------
__device__ float g_q[(size_t)TOK * HID];
__device__ float g_k[(size_t)TOK * HID];
__device__ float g_v[(size_t)TOK * HID];
__device__ __nv_bfloat16 g_x_hi[(size_t)TOK * INDIM];
__device__ __nv_bfloat16 g_x_lo[(size_t)TOK * INDIM];
__device__ __nv_bfloat16 g_oh[(size_t)TOK * HID];
__device__ __nv_bfloat16 g_ol[(size_t)TOK * HID];
__device__ __nv_bfloat16 g_wq_hi[(size_t)HID * INDIM];
__device__ __nv_bfloat16 g_wq_lo[(size_t)HID * INDIM];
__device__ __nv_bfloat16 g_wk_hi[(size_t)HID * INDIM];
__device__ __nv_bfloat16 g_wk_lo[(size_t)HID * INDIM];
__device__ __nv_bfloat16 g_wv_hi[(size_t)HID * INDIM];
__device__ __nv_bfloat16 g_wv_lo[(size_t)HID * INDIM];
__device__ __nv_bfloat16 g_wo_hi[(size_t)INDIM * HID];
__device__ __nv_bfloat16 g_wo_lo[(size_t)INDIM * HID];

// ---------------- helpers ----------------
__device__ __forceinline__ uint32_t smem_u32(const void* p) {
    uint32_t a;
    asm("{ .reg .u64 t; cvta.to.shared.u64 t, %1; cvt.u32.u64 %0, t; }" : "=r"(a) : "l"(p));
    return a;
}

__device__ __forceinline__ void cp16(uint32_t dst, const void* src) {
    asm volatile("cp.async.cg.shared.global [%0], [%1], 16;" :: "r"(dst), "l"(src) : "memory");
}
#define CP_COMMIT() asm volatile("cp.async.commit_group;" ::: "memory")
#define CP_WAIT(n)  asm volatile("cp.async.wait_group %0;" :: "n"(n) : "memory")

#define LDSM_X4(r, a) \
    asm volatile("ldmatrix.sync.aligned.m8n8.x4.shared.b16 {%0,%1,%2,%3}, [%4];" \
        : "=r"((r)[0]), "=r"((r)[1]), "=r"((r)[2]), "=r"((r)[3]) : "r"(a))

__device__ __forceinline__ void mma16816(float* d, const uint32_t* a, uint32_t b0, uint32_t b1) {
    asm volatile("mma.sync.aligned.m16n8k16.row.col.f32.bf16.bf16.f32 "
        "{%0,%1,%2,%3}, {%4,%5,%6,%7}, {%8,%9}, {%0,%1,%2,%3};"
        : "+f"(d[0]), "+f"(d[1]), "+f"(d[2]), "+f"(d[3])
        : "r"(a[0]), "r"(a[1]), "r"(a[2]), "r"(a[3]), "r"(b0), "r"(b1));
}

__device__ __forceinline__ uint32_t split2(float a, float b, uint32_t& lo) {
    __nv_bfloat16 ha = __float2bfloat16_rn(a), hb = __float2bfloat16_rn(b);
    float ra = a - __bfloat162float(ha), rb = b - __bfloat162float(hb);
    __nv_bfloat16 la = __float2bfloat16_rn(ra), lb = __float2bfloat16_rn(rb);
    lo = (uint32_t)(*(uint16_t*)&la) | ((uint32_t)(*(uint16_t*)&lb) << 16);
    return (uint32_t)(*(uint16_t*)&ha) | ((uint32_t)(*(uint16_t*)&hb) << 16);
}

// =====================================================================
// conversions (one-time per launch)
// =====================================================================
__global__ void convert_x(const float* __restrict__ x)
{
    size_t i2 = (size_t)blockIdx.x * 256 + threadIdx.x;
    size_t idx = i2 * 2;
    int d  = (int)(idx & 63);
    int hw = (int)((idx >> 6) & 1023);
    int r  = (int)(idx >> 16);        // b*96 + t
    int t  = r % 96, b = r / 96;
    int sg = t / 24, p = t - sg * 24;
    int m  = ((b * 1024 + hw) << 2) + sg;
    int k  = p * 64 + d;
    float2 v = *(const float2*)(x + idx);
    uint32_t lo, hi = split2(v.x, v.y, lo);
    size_t o = (size_t)m * INDIM + k;
    *(uint32_t*)(g_x_hi + o) = hi;
    *(uint32_t*)(g_x_lo + o) = lo;
}

__global__ void convert_qkv(const float* __restrict__ Wq,
                            const float* __restrict__ Wk,
                            const float* __restrict__ Wv)
{
    const int z = blockIdx.y;
    const float* W = (z == 0) ? Wq : ((z == 1) ? Wk : Wv);
    __nv_bfloat16* oh = (z == 0) ? g_wq_hi : ((z == 1) ? g_wk_hi : g_wv_hi);
    __nv_bfloat16* ol = (z == 0) ? g_wq_lo : ((z == 1) ? g_wk_lo : g_wv_lo);
    int idx = blockIdx.x * 256 + threadIdx.x;      // n*INDIM + k
    int n = idx / INDIM, k = idx - n * INDIM;
    float v = W[(size_t)k * HID + n];
    __nv_bfloat16 h = __float2bfloat16_rn(v);
    oh[idx] = h;
    ol[idx] = __float2bfloat16_rn(v - __bfloat162float(h));
}

__global__ void convert_wo(const float* __restrict__ Wo)
{
    int idx = blockIdx.x * 256 + threadIdx.x;      // e*HID + k
    int e = idx / HID, k = idx - e * HID;
    float v = Wo[(size_t)k * INDIM + e];
    __nv_bfloat16 h = __float2bfloat16_rn(v);
    g_wo_hi[idx] = h;
    g_wo_lo[idx] = __float2bfloat16_rn(v - __bfloat162float(h));
}

// =====================================================================
// Kernel 1: QKV GEMM, mma.sync bf16 split-3, pass-major MMA order.
// CTA tile 128(M)x64(N), K-chunk 16, 3 stages, 256 threads, 3 CTAs/SM.
// grid (12, 256, 3).
// =====================================================================
__global__ __launch_bounds__(256, 3) void gemm_qkv_mma()
{
    __shared__ __nv_bfloat16 sAh[3][128][24];
    __shared__ __nv_bfloat16 sAl[3][128][24];
    __shared__ __nv_bfloat16 sBh[3][64][24];
    __shared__ __nv_bfloat16 sBl[3][64][24];

    const int tid = threadIdx.x;
    const int n0 = blockIdx.x * 64, m0 = blockIdx.y * 128, z = blockIdx.z;
    const __nv_bfloat16* Bhi = (z == 0) ? g_wq_hi : ((z == 1) ? g_wk_hi : g_wv_hi);
    const __nv_bfloat16* Blo = (z == 0) ? g_wq_lo : ((z == 1) ? g_wk_lo : g_wv_lo);
    float* C = (z == 0) ? g_q : ((z == 1) ? g_k : g_v);

    const int arow = tid >> 1, ahalf = tid & 1;
    const int brow = tid >> 2, bhalf = (tid >> 1) & 1, bgrp = tid & 1;
    const __nv_bfloat16* asrch = g_x_hi + (size_t)(m0 + arow) * INDIM + ahalf * 8;
    const __nv_bfloat16* asrcl = g_x_lo + (size_t)(m0 + arow) * INDIM + ahalf * 8;
    const __nv_bfloat16* bsrc  = (bgrp ? Blo : Bhi) + (size_t)(n0 + brow) * INDIM + bhalf * 8;

    const int wid = tid >> 5, lane = tid & 31;
    const int wm = wid & 3, wn = wid >> 2;
    const int aldr = wm * 32 + (lane & 15);
    const int aldc = (lane >> 4) * 8;
    const int bldr = wn * 32 + ((lane >> 4) & 1) * 8 + (lane & 7);
    const int bldc = ((lane >> 3) & 1) * 8;

    float acc[2][4][4];
    #pragma unroll
    for (int mi = 0; mi < 2; mi++)
        #pragma unroll
        for (int ni = 0; ni < 4; ni++)
            #pragma unroll
            for (int q = 0; q < 4; q++) acc[mi][ni][q] = 0.f;

    const int NC = INDIM / 16;   // 96

    #define STAGE(st, c) do {                                                     \
        cp16(smem_u32(&sAh[st][arow][ahalf * 8]), asrch + (c) * 16);              \
        cp16(smem_u32(&sAl[st][arow][ahalf * 8]), asrcl + (c) * 16);              \
        cp16(smem_u32(&(bgrp ? sBl : sBh)[st][brow][bhalf * 8]), bsrc + (c) * 16);\
    } while (0)

    STAGE(0, 0); CP_COMMIT();
    STAGE(1, 1); CP_COMMIT();

    int sc_ = 0;   // stage of chunk c
    for (int c = 0; c < NC; c++) {
        CP_WAIT(1);
        __syncthreads();
        int sn = sc_ + 2; if (sn >= 3) sn -= 3;
        if (c + 2 < NC) { STAGE(sn, c + 2); CP_COMMIT(); }

        uint32_t ah[2][4], al[2][4], bh[2][4], bl[2][4];
        #pragma unroll
        for (int mi = 0; mi < 2; mi++) {
            LDSM_X4(ah[mi], smem_u32(&sAh[sc_][aldr + mi * 16][aldc]));
            LDSM_X4(al[mi], smem_u32(&sAl[sc_][aldr + mi * 16][aldc]));
        }
        #pragma unroll
        for (int g = 0; g < 2; g++) {
            LDSM_X4(bh[g], smem_u32(&sBh[sc_][bldr + g * 16][bldc]));
            LDSM_X4(bl[g], smem_u32(&sBl[sc_][bldr + g * 16][bldc]));
        }
        // pass-major: 8 independent MMAs between accumulator reuses
        #pragma unroll
        for (int mi = 0; mi < 2; mi++)
            #pragma unroll
            for (int ni = 0; ni < 4; ni++)
                mma16816(acc[mi][ni], ah[mi],
                         bh[ni >> 1][(ni & 1) * 2], bh[ni >> 1][(ni & 1) * 2 + 1]);
        #pragma unroll
        for (int mi = 0; mi < 2; mi++)
            #pragma unroll
            for (int ni = 0; ni < 4; ni++)
                mma16816(acc[mi][ni], ah[mi],
                         bl[ni >> 1][(ni & 1) * 2], bl[ni >> 1][(ni & 1) * 2 + 1]);
        #pragma unroll
        for (int mi = 0; mi < 2; mi++)
            #pragma unroll
            for (int ni = 0; ni < 4; ni++)
                mma16816(acc[mi][ni], al[mi],
                         bh[ni >> 1][(ni & 1) * 2], bh[ni >> 1][(ni & 1) * 2 + 1]);
        if (++sc_ == 3) sc_ = 0;
    }
    #undef STAGE

    // epilogue: contiguous fp32 stores
    #pragma unroll
    for (int mi = 0; mi < 2; mi++) {
        int r = m0 + wm * 32 + mi * 16 + (lane >> 2);
        #pragma unroll
        for (int ni = 0; ni < 4; ni++) {
            int cg = n0 + wn * 32 + ni * 8 + (lane & 3) * 2;
            *(float2*)(C + (size_t)r * HID + cg)       = make_float2(acc[mi][ni][0], acc[mi][ni][1]);
            *(float2*)(C + (size_t)(r + 8) * HID + cg) = make_float2(acc[mi][ni][2], acc[mi][ni][3]);
        }
    }
}

// =====================================================================
// Kernel 2: RoPE + tiny attention; emits o as bf16 hi/lo.
// =====================================================================
__global__ __launch_bounds__(256)
void attn_kernel(const float* __restrict__ fcos, const float* __restrict__ fsin)
{
    __shared__ float sq[NSEG][HID];
    __shared__ float sk[NSEG][HID];
    __shared__ float sv[NSEG][HID];

    const int bhw = blockIdx.x;
    const int tid = threadIdx.x;
    const long base = (long)bhw * NSEG * HID;

    for (int idx = tid; idx < NSEG * (HID / 2); idx += 256) {
        int i = idx / (HID / 2);
        int j = idx - i * (HID / 2);
        float c = fcos[i * (HID / 2) + j];
        float s = fsin[i * (HID / 2) + j];
        float2 q2 = *(const float2*)(g_q + base + (long)i * HID + 2 * j);
        float2 k2 = *(const float2*)(g_k + base + (long)i * HID + 2 * j);
        sq[i][2 * j]     = q2.x * c - q2.y * s;
        sq[i][2 * j + 1] = q2.x * s + q2.y * c;
        sk[i][2 * j]     = k2.x * c - k2.y * s;
        sk[i][2 * j + 1] = k2.x * s + k2.y * c;
        float2 v2 = *(const float2*)(g_v + base + (long)i * HID + 2 * j);
        *(float2*)&sv[i][2 * j] = v2;
    }
    __syncthreads();

    const int w = tid >> 5;
    const int lane = tid & 31;
    const int cb = w * HD;

    float sc[4][4];
    #pragma unroll
    for (int i = 0; i < 4; i++)
        #pragma unroll
        for (int j = 0; j < 4; j++) {
            float p = 0.f;
            #pragma unroll
            for (int t = 0; t < 3; t++) {
                int d = lane + 32 * t;
                p += sq[i][cb + d] * sk[j][cb + d];
            }
            sc[i][j] = p;
        }
    #pragma unroll
    for (int i = 0; i < 4; i++)
        #pragma unroll
        for (int j = 0; j < 4; j++)
            #pragma unroll
            for (int off = 16; off > 0; off >>= 1)
                sc[i][j] += __shfl_xor_sync(0xffffffffu, sc[i][j], off);

    const float scale = 0.10206207261596577f;   // 1/sqrt(96)
    float attn[4][4];
    #pragma unroll
    for (int i = 0; i < 4; i++) {
        float mx = -1e30f;
        #pragma unroll
        for (int j = 0; j < 4; j++) { sc[i][j] *= scale; mx = fmaxf(mx, sc[i][j]); }
        float sum = 0.f;
        #pragma unroll
        for (int j = 0; j < 4; j++) { attn[i][j] = expf(sc[i][j] - mx); sum += attn[i][j]; }
        float inv = 1.f / sum;
        #pragma unroll
        for (int j = 0; j < 4; j++) attn[i][j] *= inv;
    }

    #pragma unroll
    for (int i = 0; i < 4; i++) {
        #pragma unroll
        for (int t = 0; t < 3; t++) {
            int d = lane + 32 * t;
            float o = 0.f;
            #pragma unroll
            for (int j = 0; j < 4; j++) o += attn[i][j] * sv[j][cb + d];
            long oi = base + (long)i * HID + cb + d;
            __nv_bfloat16 h = __float2bfloat16_rn(o);
            g_oh[oi] = h;
            g_ol[oi] = __float2bfloat16_rn(o - __bfloat162float(h));
        }
    }
}

// =====================================================================
// Kernel 3: O-proj GEMM, mma.sync bf16 split-3, pass-major MMA order.
// CTA tile 128x64, K-chunk 16, 3 stages, 256 threads, 3 CTAs/SM.
// grid (24, 256).
// =====================================================================
__global__ __launch_bounds__(256, 3) void gemm_o_mma(const float* __restrict__ bo,
                                                     float* __restrict__ out)
{
    __shared__ __nv_bfloat16 sAh[3][128][24];
    __shared__ __nv_bfloat16 sAl[3][128][24];
    __shared__ __nv_bfloat16 sBh[3][64][24];
    __shared__ __nv_bfloat16 sBl[3][64][24];

    const int tid = threadIdx.x;
    const int n0 = blockIdx.x * 64, m0 = blockIdx.y * 128;

    const int arow = tid >> 1, ahalf = tid & 1;
    const int brow = tid >> 2, bhalf = (tid >> 1) & 1, bgrp = tid & 1;
    const __nv_bfloat16* asrch = g_oh + (size_t)(m0 + arow) * HID + ahalf * 8;
    const __nv_bfloat16* asrcl = g_ol + (size_t)(m0 + arow) * HID + ahalf * 8;
    const __nv_bfloat16* bsrc  = (bgrp ? g_wo_lo : g_wo_hi) + (size_t)(n0 + brow) * HID + bhalf * 8;

    const int wid = tid >> 5, lane = tid & 31;
    const int wm = wid & 3, wn = wid >> 2;
    const int aldr = wm * 32 + (lane & 15);
    const int aldc = (lane >> 4) * 8;
    const int bldr = wn * 32 + ((lane >> 4) & 1) * 8 + (lane & 7);
    const int bldc = ((lane >> 3) & 1) * 8;

    float acc[2][4][4];
    #pragma unroll
    for (int mi = 0; mi < 2; mi++)
        #pragma unroll
        for (int ni = 0; ni < 4; ni++)
            #pragma unroll
            for (int q = 0; q < 4; q++) acc[mi][ni][q] = 0.f;

    const int NC = HID / 16;   // 48

    #define STAGE(st, c) do {                                                     \
        cp16(smem_u32(&sAh[st][arow][ahalf * 8]), asrch + (c) * 16);              \
        cp16(smem_u32(&sAl[st][arow][ahalf * 8]), asrcl + (c) * 16);              \
        cp16(smem_u32(&(bgrp ? sBl : sBh)[st][brow][bhalf * 8]), bsrc + (c) * 16);\
    } while (0)

    STAGE(0, 0); CP_COMMIT();
    STAGE(1, 1); CP_COMMIT();

    int sc_ = 0;
    for (int c = 0; c < NC; c++) {
        CP_WAIT(1);
        __syncthreads();
        int sn = sc_ + 2; if (sn >= 3) sn -= 3;
        if (c + 2 < NC) { STAGE(sn, c + 2); CP_COMMIT(); }

        uint32_t ah[2][4], al[2][4], bh[2][4], bl[2][4];
        #pragma unroll
        for (int mi = 0; mi < 2; mi++) {
            LDSM_X4(ah[mi], smem_u32(&sAh[sc_][aldr + mi * 16][aldc]));
            LDSM_X4(al[mi], smem_u32(&sAl[sc_][aldr + mi * 16][aldc]));
        }
        #pragma unroll
        for (int g = 0; g < 2; g++) {
            LDSM_X4(bh[g], smem_u32(&sBh[sc_][bldr + g * 16][bldc]));
            LDSM_X4(bl[g], smem_u32(&sBl[sc_][bldr + g * 16][bldc]));
        }
        #pragma unroll
        for (int mi = 0; mi < 2; mi++)
            #pragma unroll
            for (int ni = 0; ni < 4; ni++)
                mma16816(acc[mi][ni], ah[mi],
                         bh[ni >> 1][(ni & 1) * 2], bh[ni >> 1][(ni & 1) * 2 + 1]);
        #pragma unroll
        for (int mi = 0; mi < 2; mi++)
            #pragma unroll
            for (int ni = 0; ni < 4; ni++)
                mma16816(acc[mi][ni], ah[mi],
                         bl[ni >> 1][(ni & 1) * 2], bl[ni >> 1][(ni & 1) * 2 + 1]);
        #pragma unroll
        for (int mi = 0; mi < 2; mi++)
            #pragma unroll
            for (int ni = 0; ni < 4; ni++)
                mma16816(acc[mi][ni], al[mi],
                         bh[ni >> 1][(ni & 1) * 2], bh[ni >> 1][(ni & 1) * 2 + 1]);
        if (++sc_ == 3) sc_ = 0;
    }
    #undef STAGE

    // epilogue: + bias, scatter to (B,T,H,W,D)
    #pragma unroll
    for (int mi = 0; mi < 2; mi++) {
        #pragma unroll
        for (int half = 0; half < 2; half++) {
            int m = m0 + wm * 32 + mi * 16 + (lane >> 2) + half * 8;
            int bhw = m >> 2, sg = m & 3, b = bhw >> 10, hw = bhw & 1023;
            long baseO = ((long)(b * 96 + sg * 24) * 1024 + hw) * 64;
            #pragma unroll
            for (int ni = 0; ni < 4; ni++) {
                int e = n0 + wn * 32 + ni * 8 + (lane & 3) * 2;
                int p = e >> 6, d = e & 63;
                float2 bb = *(const float2*)(bo + e);
                float2 v = make_float2(acc[mi][ni][half * 2]     + bb.x,
                                       acc[mi][ni][half * 2 + 1] + bb.y);
                *(float2*)(out + baseO + (long)p * 65536 + d) = v;
            }
        }
    }
}

// =====================================================================
extern "C" void kernel_launch(void* const* d_in, const int* in_sizes, int n_in,
                              void* d_out, int out_size)
{
    const float* x  = (const float*)d_in[0];
    const float* fc = (const float*)d_in[1];
    const float* fs = (const float*)d_in[2];
    const float* Wq = (const float*)d_in[3];
    const float* Wk = (const float*)d_in[4];
    const float* Wv = (const float*)d_in[5];
    const float* Wo = (const float*)d_in[6];
    const float* bo = (const float*)d_in[7];
    float* out = (float*)d_out;

    convert_qkv<<<dim3((HID * INDIM) / 256, 3), 256>>>(Wq, Wk, Wv);
    convert_wo<<<(INDIM * HID) / 256, 256>>>(Wo);
    convert_x<<<(TOK * (size_t)INDIM / 2) / 256, 256>>>(x);
    gemm_qkv_mma<<<dim3(HID / 64, TOK / 128, 3), 256>>>();
    attn_kernel<<<BHW, 256>>>(fc, fs);
    gemm_o_mma<<<dim3(INDIM / 64, TOK / 128), 256>>>(bo, out);
}

// round 15
// speedup vs baseline: 1.0019x; 1.0018x over previous
#include <cuda_runtime.h>
#include <cuda_bf16.h>
#include <cstdint>

// ---------------- problem constants ----------------
#define TOK    32768
#define BHW    8192
#define NSEG   4
#define INDIM  1536
#define HID    768
#define NHEAD  8
#define HD     96

// ---------------- scratch ----------------
__device__ float g_q[(size_t)TOK * HID];
__device__ float g_k[(size_t)TOK * HID];
__device__ float g_v[(size_t)TOK * HID];
__device__ __nv_bfloat16 g_x_hi[(size_t)TOK * INDIM];
__device__ __nv_bfloat16 g_x_lo[(size_t)TOK * INDIM];
__device__ __nv_bfloat16 g_oh[(size_t)TOK * HID];
__device__ __nv_bfloat16 g_ol[(size_t)TOK * HID];
__device__ __nv_bfloat16 g_wq_hi[(size_t)HID * INDIM];
__device__ __nv_bfloat16 g_wq_lo[(size_t)HID * INDIM];
__device__ __nv_bfloat16 g_wk_hi[(size_t)HID * INDIM];
__device__ __nv_bfloat16 g_wk_lo[(size_t)HID * INDIM];
__device__ __nv_bfloat16 g_wv_hi[(size_t)HID * INDIM];
__device__ __nv_bfloat16 g_wv_lo[(size_t)HID * INDIM];
__device__ __nv_bfloat16 g_wo_hi[(size_t)INDIM * HID];
__device__ __nv_bfloat16 g_wo_lo[(size_t)INDIM * HID];

// ---------------- helpers ----------------
__device__ __forceinline__ uint32_t smem_u32(const void* p) {
    uint32_t a;
    asm("{ .reg .u64 t; cvta.to.shared.u64 t, %1; cvt.u32.u64 %0, t; }" : "=r"(a) : "l"(p));
    return a;
}

__device__ __forceinline__ void cp16(uint32_t dst, const void* src) {
    asm volatile("cp.async.cg.shared.global [%0], [%1], 16;" :: "r"(dst), "l"(src) : "memory");
}
#define CP_COMMIT() asm volatile("cp.async.commit_group;" ::: "memory")
#define CP_WAIT(n)  asm volatile("cp.async.wait_group %0;" :: "n"(n) : "memory")

#define LDSM_X4(r, a) \
    asm volatile("ldmatrix.sync.aligned.m8n8.x4.shared.b16 {%0,%1,%2,%3}, [%4];" \
        : "=r"((r)[0]), "=r"((r)[1]), "=r"((r)[2]), "=r"((r)[3]) : "r"(a))

__device__ __forceinline__ void mma16816(float* d, const uint32_t* a, uint32_t b0, uint32_t b1) {
    asm volatile("mma.sync.aligned.m16n8k16.row.col.f32.bf16.bf16.f32 "
        "{%0,%1,%2,%3}, {%4,%5,%6,%7}, {%8,%9}, {%0,%1,%2,%3};"
        : "+f"(d[0]), "+f"(d[1]), "+f"(d[2]), "+f"(d[3])
        : "r"(a[0]), "r"(a[1]), "r"(a[2]), "r"(a[3]), "r"(b0), "r"(b1));
}

__device__ __forceinline__ uint32_t split2(float a, float b, uint32_t& lo) {
    __nv_bfloat16 ha = __float2bfloat16_rn(a), hb = __float2bfloat16_rn(b);
    float ra = a - __bfloat162float(ha), rb = b - __bfloat162float(hb);
    __nv_bfloat16 la = __float2bfloat16_rn(ra), lb = __float2bfloat16_rn(rb);
    lo = (uint32_t)(*(uint16_t*)&la) | ((uint32_t)(*(uint16_t*)&lb) << 16);
    return (uint32_t)(*(uint16_t*)&ha) | ((uint32_t)(*(uint16_t*)&hb) << 16);
}

// =====================================================================
// conversions (one-time per launch)
// =====================================================================
__global__ void convert_x(const float* __restrict__ x)
{
    size_t i2 = (size_t)blockIdx.x * 256 + threadIdx.x;
    size_t idx = i2 * 2;
    int d  = (int)(idx & 63);
    int hw = (int)((idx >> 6) & 1023);
    int r  = (int)(idx >> 16);        // b*96 + t
    int t  = r % 96, b = r / 96;
    int sg = t / 24, p = t - sg * 24;
    int m  = ((b * 1024 + hw) << 2) + sg;
    int k  = p * 64 + d;
    float2 v = *(const float2*)(x + idx);
    uint32_t lo, hi = split2(v.x, v.y, lo);
    size_t o = (size_t)m * INDIM + k;
    *(uint32_t*)(g_x_hi + o) = hi;
    *(uint32_t*)(g_x_lo + o) = lo;
}

__global__ void convert_qkv(const float* __restrict__ Wq,
                            const float* __restrict__ Wk,
                            const float* __restrict__ Wv)
{
    const int z = blockIdx.y;
    const float* W = (z == 0) ? Wq : ((z == 1) ? Wk : Wv);
    __nv_bfloat16* oh = (z == 0) ? g_wq_hi : ((z == 1) ? g_wk_hi : g_wv_hi);
    __nv_bfloat16* ol = (z == 0) ? g_wq_lo : ((z == 1) ? g_wk_lo : g_wv_lo);
    int idx = blockIdx.x * 256 + threadIdx.x;      // n*INDIM + k
    int n = idx / INDIM, k = idx - n * INDIM;
    float v = W[(size_t)k * HID + n];
    __nv_bfloat16 h = __float2bfloat16_rn(v);
    oh[idx] = h;
    ol[idx] = __float2bfloat16_rn(v - __bfloat162float(h));
}

__global__ void convert_wo(const float* __restrict__ Wo)
{
    int idx = blockIdx.x * 256 + threadIdx.x;      // e*HID + k
    int e = idx / HID, k = idx - e * HID;
    float v = Wo[(size_t)k * INDIM + e];
    __nv_bfloat16 h = __float2bfloat16_rn(v);
    g_wo_hi[idx] = h;
    g_wo_lo[idx] = __float2bfloat16_rn(v - __bfloat162float(h));
}

// =====================================================================
// Kernel 1: QKV GEMM, mma.sync bf16 split-3, pass-major MMA order.
// CTA tile 128(M)x64(N), K-chunk 16, 3 stages, 256 threads, 3 CTAs/SM.
// grid (12, 256, 3).
// =====================================================================
__global__ __launch_bounds__(256, 3) void gemm_qkv_mma()
{
    __shared__ __nv_bfloat16 sAh[3][128][24];
    __shared__ __nv_bfloat16 sAl[3][128][24];
    __shared__ __nv_bfloat16 sBh[3][64][24];
    __shared__ __nv_bfloat16 sBl[3][64][24];

    const int tid = threadIdx.x;
    const int n0 = blockIdx.x * 64, m0 = blockIdx.y * 128, z = blockIdx.z;
    const __nv_bfloat16* Bhi = (z == 0) ? g_wq_hi : ((z == 1) ? g_wk_hi : g_wv_hi);
    const __nv_bfloat16* Blo = (z == 0) ? g_wq_lo : ((z == 1) ? g_wk_lo : g_wv_lo);
    float* C = (z == 0) ? g_q : ((z == 1) ? g_k : g_v);

    const int arow = tid >> 1, ahalf = tid & 1;
    const int brow = tid >> 2, bhalf = (tid >> 1) & 1, bgrp = tid & 1;
    const __nv_bfloat16* asrch = g_x_hi + (size_t)(m0 + arow) * INDIM + ahalf * 8;
    const __nv_bfloat16* asrcl = g_x_lo + (size_t)(m0 + arow) * INDIM + ahalf * 8;
    const __nv_bfloat16* bsrc  = (bgrp ? Blo : Bhi) + (size_t)(n0 + brow) * INDIM + bhalf * 8;

    const int wid = tid >> 5, lane = tid & 31;
    const int wm = wid & 3, wn = wid >> 2;
    const int aldr = wm * 32 + (lane & 15);
    const int aldc = (lane >> 4) * 8;
    const int bldr = wn * 32 + ((lane >> 4) & 1) * 8 + (lane & 7);
    const int bldc = ((lane >> 3) & 1) * 8;

    float acc[2][4][4];
    #pragma unroll
    for (int mi = 0; mi < 2; mi++)
        #pragma unroll
        for (int ni = 0; ni < 4; ni++)
            #pragma unroll
            for (int q = 0; q < 4; q++) acc[mi][ni][q] = 0.f;

    const int NC = INDIM / 16;   // 96

    #define STAGE(st, c) do {                                                     \
        cp16(smem_u32(&sAh[st][arow][ahalf * 8]), asrch + (c) * 16);              \
        cp16(smem_u32(&sAl[st][arow][ahalf * 8]), asrcl + (c) * 16);              \
        cp16(smem_u32(&(bgrp ? sBl : sBh)[st][brow][bhalf * 8]), bsrc + (c) * 16);\
    } while (0)

    STAGE(0, 0); CP_COMMIT();
    STAGE(1, 1); CP_COMMIT();

    int sc_ = 0;   // stage of chunk c
    for (int c = 0; c < NC; c++) {
        CP_WAIT(1);
        __syncthreads();
        int sn = sc_ + 2; if (sn >= 3) sn -= 3;
        if (c + 2 < NC) { STAGE(sn, c + 2); CP_COMMIT(); }

        uint32_t ah[2][4], al[2][4], bh[2][4], bl[2][4];
        #pragma unroll
        for (int mi = 0; mi < 2; mi++) {
            LDSM_X4(ah[mi], smem_u32(&sAh[sc_][aldr + mi * 16][aldc]));
            LDSM_X4(al[mi], smem_u32(&sAl[sc_][aldr + mi * 16][aldc]));
        }
        #pragma unroll
        for (int g = 0; g < 2; g++) {
            LDSM_X4(bh[g], smem_u32(&sBh[sc_][bldr + g * 16][bldc]));
            LDSM_X4(bl[g], smem_u32(&sBl[sc_][bldr + g * 16][bldc]));
        }
        // pass-major: 8 independent MMAs between accumulator reuses
        #pragma unroll
        for (int mi = 0; mi < 2; mi++)
            #pragma unroll
            for (int ni = 0; ni < 4; ni++)
                mma16816(acc[mi][ni], ah[mi],
                         bh[ni >> 1][(ni & 1) * 2], bh[ni >> 1][(ni & 1) * 2 + 1]);
        #pragma unroll
        for (int mi = 0; mi < 2; mi++)
            #pragma unroll
            for (int ni = 0; ni < 4; ni++)
                mma16816(acc[mi][ni], ah[mi],
                         bl[ni >> 1][(ni & 1) * 2], bl[ni >> 1][(ni & 1) * 2 + 1]);
        #pragma unroll
        for (int mi = 0; mi < 2; mi++)
            #pragma unroll
            for (int ni = 0; ni < 4; ni++)
                mma16816(acc[mi][ni], al[mi],
                         bh[ni >> 1][(ni & 1) * 2], bh[ni >> 1][(ni & 1) * 2 + 1]);
        if (++sc_ == 3) sc_ = 0;
    }
    #undef STAGE

    // epilogue: contiguous fp32 stores
    #pragma unroll
    for (int mi = 0; mi < 2; mi++) {
        int r = m0 + wm * 32 + mi * 16 + (lane >> 2);
        #pragma unroll
        for (int ni = 0; ni < 4; ni++) {
            int cg = n0 + wn * 32 + ni * 8 + (lane & 3) * 2;
            *(float2*)(C + (size_t)r * HID + cg)       = make_float2(acc[mi][ni][0], acc[mi][ni][1]);
            *(float2*)(C + (size_t)(r + 8) * HID + cg) = make_float2(acc[mi][ni][2], acc[mi][ni][3]);
        }
    }
}

// =====================================================================
// Kernel 2: RoPE + tiny attention; emits o as bf16 hi/lo.
// =====================================================================
__global__ __launch_bounds__(256)
void attn_kernel(const float* __restrict__ fcos, const float* __restrict__ fsin)
{
    __shared__ float sq[NSEG][HID];
    __shared__ float sk[NSEG][HID];
    __shared__ float sv[NSEG][HID];

    const int bhw = blockIdx.x;
    const int tid = threadIdx.x;
    const long base = (long)bhw * NSEG * HID;

    for (int idx = tid; idx < NSEG * (HID / 2); idx += 256) {
        int i = idx / (HID / 2);
        int j = idx - i * (HID / 2);
        float c = fcos[i * (HID / 2) + j];
        float s = fsin[i * (HID / 2) + j];
        float2 q2 = *(const float2*)(g_q + base + (long)i * HID + 2 * j);
        float2 k2 = *(const float2*)(g_k + base + (long)i * HID + 2 * j);
        sq[i][2 * j]     = q2.x * c - q2.y * s;
        sq[i][2 * j + 1] = q2.x * s + q2.y * c;
        sk[i][2 * j]     = k2.x * c - k2.y * s;
        sk[i][2 * j + 1] = k2.x * s + k2.y * c;
        float2 v2 = *(const float2*)(g_v + base + (long)i * HID + 2 * j);
        *(float2*)&sv[i][2 * j] = v2;
    }
    __syncthreads();

    const int w = tid >> 5;
    const int lane = tid & 31;
    const int cb = w * HD;

    float sc[4][4];
    #pragma unroll
    for (int i = 0; i < 4; i++)
        #pragma unroll
        for (int j = 0; j < 4; j++) {
            float p = 0.f;
            #pragma unroll
            for (int t = 0; t < 3; t++) {
                int d = lane + 32 * t;
                p += sq[i][cb + d] * sk[j][cb + d];
            }
            sc[i][j] = p;
        }
    #pragma unroll
    for (int i = 0; i < 4; i++)
        #pragma unroll
        for (int j = 0; j < 4; j++)
            #pragma unroll
            for (int off = 16; off > 0; off >>= 1)
                sc[i][j] += __shfl_xor_sync(0xffffffffu, sc[i][j], off);

    const float scale = 0.10206207261596577f;   // 1/sqrt(96)
    float attn[4][4];
    #pragma unroll
    for (int i = 0; i < 4; i++) {
        float mx = -1e30f;
        #pragma unroll
        for (int j = 0; j < 4; j++) { sc[i][j] *= scale; mx = fmaxf(mx, sc[i][j]); }
        float sum = 0.f;
        #pragma unroll
        for (int j = 0; j < 4; j++) { attn[i][j] = expf(sc[i][j] - mx); sum += attn[i][j]; }
        float inv = 1.f / sum;
        #pragma unroll
        for (int j = 0; j < 4; j++) attn[i][j] *= inv;
    }

    #pragma unroll
    for (int i = 0; i < 4; i++) {
        #pragma unroll
        for (int t = 0; t < 3; t++) {
            int d = lane + 32 * t;
            float o = 0.f;
            #pragma unroll
            for (int j = 0; j < 4; j++) o += attn[i][j] * sv[j][cb + d];
            long oi = base + (long)i * HID + cb + d;
            __nv_bfloat16 h = __float2bfloat16_rn(o);
            g_oh[oi] = h;
            g_ol[oi] = __float2bfloat16_rn(o - __bfloat162float(h));
        }
    }
}

// =====================================================================
// Kernel 3: O-proj GEMM, mma.sync bf16 split-3, pass-major MMA order.
// CTA tile 128x64, K-chunk 16, 3 stages, 256 threads, 3 CTAs/SM.
// grid (24, 256).
// =====================================================================
__global__ __launch_bounds__(256, 3) void gemm_o_mma(const float* __restrict__ bo,
                                                     float* __restrict__ out)
{
    __shared__ __nv_bfloat16 sAh[3][128][24];
    __shared__ __nv_bfloat16 sAl[3][128][24];
    __shared__ __nv_bfloat16 sBh[3][64][24];
    __shared__ __nv_bfloat16 sBl[3][64][24];

    const int tid = threadIdx.x;
    const int n0 = blockIdx.x * 64, m0 = blockIdx.y * 128;

    const int arow = tid >> 1, ahalf = tid & 1;
    const int brow = tid >> 2, bhalf = (tid >> 1) & 1, bgrp = tid & 1;
    const __nv_bfloat16* asrch = g_oh + (size_t)(m0 + arow) * HID + ahalf * 8;
    const __nv_bfloat16* asrcl = g_ol + (size_t)(m0 + arow) * HID + ahalf * 8;
    const __nv_bfloat16* bsrc  = (bgrp ? g_wo_lo : g_wo_hi) + (size_t)(n0 + brow) * HID + bhalf * 8;

    const int wid = tid >> 5, lane = tid & 31;
    const int wm = wid & 3, wn = wid >> 2;
    const int aldr = wm * 32 + (lane & 15);
    const int aldc = (lane >> 4) * 8;
    const int bldr = wn * 32 + ((lane >> 4) & 1) * 8 + (lane & 7);
    const int bldc = ((lane >> 3) & 1) * 8;

    float acc[2][4][4];
    #pragma unroll
    for (int mi = 0; mi < 2; mi++)
        #pragma unroll
        for (int ni = 0; ni < 4; ni++)
            #pragma unroll
            for (int q = 0; q < 4; q++) acc[mi][ni][q] = 0.f;

    const int NC = HID / 16;   // 48

    #define STAGE(st, c) do {                                                     \
        cp16(smem_u32(&sAh[st][arow][ahalf * 8]), asrch + (c) * 16);              \
        cp16(smem_u32(&sAl[st][arow][ahalf * 8]), asrcl + (c) * 16);              \
        cp16(smem_u32(&(bgrp ? sBl : sBh)[st][brow][bhalf * 8]), bsrc + (c) * 16);\
    } while (0)

    STAGE(0, 0); CP_COMMIT();
    STAGE(1, 1); CP_COMMIT();

    int sc_ = 0;
    for (int c = 0; c < NC; c++) {
        CP_WAIT(1);
        __syncthreads();
        int sn = sc_ + 2; if (sn >= 3) sn -= 3;
        if (c + 2 < NC) { STAGE(sn, c + 2); CP_COMMIT(); }

        uint32_t ah[2][4], al[2][4], bh[2][4], bl[2][4];
        #pragma unroll
        for (int mi = 0; mi < 2; mi++) {
            LDSM_X4(ah[mi], smem_u32(&sAh[sc_][aldr + mi * 16][aldc]));
            LDSM_X4(al[mi], smem_u32(&sAl[sc_][aldr + mi * 16][aldc]));
        }
        #pragma unroll
        for (int g = 0; g < 2; g++) {
            LDSM_X4(bh[g], smem_u32(&sBh[sc_][bldr + g * 16][bldc]));
            LDSM_X4(bl[g], smem_u32(&sBl[sc_][bldr + g * 16][bldc]));
        }
        #pragma unroll
        for (int mi = 0; mi < 2; mi++)
            #pragma unroll
            for (int ni = 0; ni < 4; ni++)
                mma16816(acc[mi][ni], ah[mi],
                         bh[ni >> 1][(ni & 1) * 2], bh[ni >> 1][(ni & 1) * 2 + 1]);
        #pragma unroll
        for (int mi = 0; mi < 2; mi++)
            #pragma unroll
            for (int ni = 0; ni < 4; ni++)
                mma16816(acc[mi][ni], ah[mi],
                         bl[ni >> 1][(ni & 1) * 2], bl[ni >> 1][(ni & 1) * 2 + 1]);
        #pragma unroll
        for (int mi = 0; mi < 2; mi++)
            #pragma unroll
            for (int ni = 0; ni < 4; ni++)
                mma16816(acc[mi][ni], al[mi],
                         bh[ni >> 1][(ni & 1) * 2], bh[ni >> 1][(ni & 1) * 2 + 1]);
        if (++sc_ == 3) sc_ = 0;
    }
    #undef STAGE

    // epilogue: + bias, scatter to (B,T,H,W,D)
    #pragma unroll
    for (int mi = 0; mi < 2; mi++) {
        #pragma unroll
        for (int half = 0; half < 2; half++) {
            int m = m0 + wm * 32 + mi * 16 + (lane >> 2) + half * 8;
            int bhw = m >> 2, sg = m & 3, b = bhw >> 10, hw = bhw & 1023;
            long baseO = ((long)(b * 96 + sg * 24) * 1024 + hw) * 64;
            #pragma unroll
            for (int ni = 0; ni < 4; ni++) {
                int e = n0 + wn * 32 + ni * 8 + (lane & 3) * 2;
                int p = e >> 6, d = e & 63;
                float2 bb = *(const float2*)(bo + e);
                float2 v = make_float2(acc[mi][ni][half * 2]     + bb.x,
                                       acc[mi][ni][half * 2 + 1] + bb.y);
                *(float2*)(out + baseO + (long)p * 65536 + d) = v;
            }
        }
    }
}

// =====================================================================
extern "C" void kernel_launch(void* const* d_in, const int* in_sizes, int n_in,
                              void* d_out, int out_size)
{
    const float* x  = (const float*)d_in[0];
    const float* fc = (const float*)d_in[1];
    const float* fs = (const float*)d_in[2];
    const float* Wq = (const float*)d_in[3];
    const float* Wk = (const float*)d_in[4];
    const float* Wv = (const float*)d_in[5];
    const float* Wo = (const float*)d_in[6];
    const float* bo = (const float*)d_in[7];
    float* out = (float*)d_out;

    convert_qkv<<<dim3((HID * INDIM) / 256, 3), 256>>>(Wq, Wk, Wv);
    convert_wo<<<(INDIM * HID) / 256, 256>>>(Wo);
    convert_x<<<(TOK * (size_t)INDIM / 2) / 256, 256>>>(x);
    gemm_qkv_mma<<<dim3(HID / 64, TOK / 128, 3), 256>>>();
    attn_kernel<<<BHW, 256>>>(fc, fs);
    gemm_o_mma<<<dim3(INDIM / 64, TOK / 128), 256>>>(bo, out);
}